// round 12
// baseline (speedup 1.0000x reference)
#include <cuda_runtime.h>

// CosinLoss fully fused, single kernel: loss = mean_i(1 - cos(pc_i, aug_i)).
// N=16384 rows, D=1024 fp32 (128 MiB streamed).
// Main loop (proven shape): 4 rows per 256-thread CTA (64 thr/row,
// 4 float4/tensor/thread -> MLP_p1=8), grid 4096, __ldcs streaming loads.
//
// Epilogue (minimal): worker lane0 does STG.32 of its fp32 partial +
// red.release.gpu.add.u32 on a counter (release orders the STG before the
// count tick; no fence, no return wait, no fp64). A poller CTA acquire-polls
// the counter to GRID1, then its 256 threads reduce the 4096 partials in fixed
// order (bit-deterministic), write the mean, and reset the counter for replay.

#define CL_N   16384
#define CL_D   1024
#define CL_EPS 1e-12f
#define GRID1  4096

__device__ __align__(16) float g_part[GRID1];
__device__ unsigned int g_count = 0;

__global__ __launch_bounds__(256)
void cos_loss_fused(const float* __restrict__ pc, const float* __restrict__ aug,
                    float* __restrict__ out) {
    const int t = threadIdx.x;

    // ---------------- Poller CTA (last block) ----------------
    if (blockIdx.x == GRID1) {
        if (t == 0) {
            unsigned int v;
            do {
                asm volatile("ld.acquire.gpu.global.u32 %0, [%1];"
                             : "=r"(v) : "l"(&g_count) : "memory");
                if (v == GRID1) break;
                __nanosleep(64);
            } while (true);
        }
        __syncthreads();   // all 256 threads wait for thread 0's poll

        // Fixed-order deterministic reduce of 4096 fp32 partials (L2-resident).
        float s = 0.0f;
        #pragma unroll
        for (int i = 0; i < GRID1 / 256; i++)      // 16 per thread
            s += __ldcg(&g_part[t + i * 256]);

        const int wid  = t >> 5;
        const int lane = t & 31;
        #pragma unroll
        for (int off = 16; off > 0; off >>= 1)
            s += __shfl_down_sync(0xFFFFFFFFu, s, off);

        __shared__ float s_sum[8];
        if (lane == 0) s_sum[wid] = s;
        __syncthreads();

        if (wid == 0) {
            s = (lane < 8) ? s_sum[lane] : 0.0f;
            #pragma unroll
            for (int off = 4; off > 0; off >>= 1)
                s += __shfl_down_sync(0xFFFFFFFFu, s, off);
            if (lane == 0) {
                out[0] = s * (1.0f / (float)CL_N);
                // Reset for next graph replay (kernel fully retires before replay).
                asm volatile("st.global.cg.u32 [%0], %1;"
                             :: "l"(&g_count), "r"(0u) : "memory");
            }
        }
        return;
    }

    // ---------------- Worker CTAs ----------------
    const int wid  = t >> 5;        // 0..7; warps 2r,2r+1 own row r
    const int lane = t & 31;
    const int rsub = t >> 6;        // 0..3: row within CTA
    const int ct   = t & 63;        // thread index within row (64 thr/row)
    const size_t row = (size_t)blockIdx.x * 4 + rsub;

    const float4* __restrict__ p4 = reinterpret_cast<const float4*>(pc  + row * CL_D);
    const float4* __restrict__ a4 = reinterpret_cast<const float4*>(aug + row * CL_D);

    // 8 outstanding LDG.128 per thread, streaming hint.
    float4 p0 = __ldcs(&p4[ct      ]);
    float4 p1 = __ldcs(&p4[ct +  64]);
    float4 p2 = __ldcs(&p4[ct + 128]);
    float4 p3 = __ldcs(&p4[ct + 192]);
    float4 a0 = __ldcs(&a4[ct      ]);
    float4 a1 = __ldcs(&a4[ct +  64]);
    float4 a2 = __ldcs(&a4[ct + 128]);
    float4 a3 = __ldcs(&a4[ct + 192]);

    float dot = p0.x*a0.x + p0.y*a0.y + p0.z*a0.z + p0.w*a0.w
              + p1.x*a1.x + p1.y*a1.y + p1.z*a1.z + p1.w*a1.w
              + p2.x*a2.x + p2.y*a2.y + p2.z*a2.z + p2.w*a2.w
              + p3.x*a3.x + p3.y*a3.y + p3.z*a3.z + p3.w*a3.w;
    float npp = p0.x*p0.x + p0.y*p0.y + p0.z*p0.z + p0.w*p0.w
              + p1.x*p1.x + p1.y*p1.y + p1.z*p1.z + p1.w*p1.w
              + p2.x*p2.x + p2.y*p2.y + p2.z*p2.z + p2.w*p2.w
              + p3.x*p3.x + p3.y*p3.y + p3.z*p3.z + p3.w*p3.w;
    float naa = a0.x*a0.x + a0.y*a0.y + a0.z*a0.z + a0.w*a0.w
              + a1.x*a1.x + a1.y*a1.y + a1.z*a1.z + a1.w*a1.w
              + a2.x*a2.x + a2.y*a2.y + a2.z*a2.z + a2.w*a2.w
              + a3.x*a3.x + a3.y*a3.y + a3.z*a3.z + a3.w*a3.w;

    #pragma unroll
    for (int off = 16; off > 0; off >>= 1) {
        dot += __shfl_down_sync(0xFFFFFFFFu, dot, off);
        npp += __shfl_down_sync(0xFFFFFFFFu, npp, off);
        naa += __shfl_down_sync(0xFFFFFFFFu, naa, off);
    }

    __shared__ float s_dot[8], s_npp[8], s_naa[8];
    if (lane == 0) {
        s_dot[wid] = dot;
        s_npp[wid] = npp;
        s_naa[wid] = naa;
    }
    __syncthreads();

    // Warp 0, lanes 0..7: slot pairs (2r, 2r+1) belong to row r.
    if (wid == 0 && lane < 8) {
        dot = s_dot[lane];
        npp = s_npp[lane];
        naa = s_naa[lane];
        dot += __shfl_xor_sync(0x000000FFu, dot, 1);
        npp += __shfl_xor_sync(0x000000FFu, npp, 1);
        naa += __shfl_xor_sync(0x000000FFu, naa, 1);

        float loss = 0.0f;
        if ((lane & 1) == 0) {
            float np_ = fmaxf(sqrtf(npp), CL_EPS);
            float na_ = fmaxf(sqrtf(naa), CL_EPS);
            loss = 1.0f - dot / (np_ * na_);
        }
        loss += __shfl_down_sync(0x000000FFu, loss, 4);
        loss += __shfl_down_sync(0x000000FFu, loss, 2);

        if (lane == 0) {
            g_part[blockIdx.x] = loss;               // plain STG.32
            // Release-RED: orders the STG above before the count tick;
            // no return value -> no L2 round-trip wait on the worker.
            asm volatile("red.release.gpu.global.add.u32 [%0], %1;"
                         :: "l"(&g_count), "r"(1u) : "memory");
        }
    }
}

extern "C" void kernel_launch(void* const* d_in, const int* in_sizes, int n_in,
                              void* d_out, int out_size) {
    const float* pc  = (const float*)d_in[0];
    const float* aug = (const float*)d_in[1];
    float* out = (float*)d_out;

    cos_loss_fused<<<GRID1 + 1, 256>>>(pc, aug, out);
}